// round 2
// baseline (speedup 1.0000x reference)
#include <cuda_runtime.h>
#include <cstdint>

#define D 128
#define NMAX 100000
#define WPITCH 132   // 128 + 4 pad: conflict-free float4 reads, 16B-aligned rows

// Scratch (allocations are forbidden; __device__ globals are the sanctioned path)
__device__ __align__(16) float g_h[(size_t)NMAX * D];
__device__ __align__(16) float g_agg[(size_t)NMAX * D];
__device__ float g_cnt[NMAX];

// ---------------------------------------------------------------------------
// Kernel 1: LayerNorm -> ReLU -> dropout mask; also zero agg and cnt.
// One warp per row, float4 per lane (128 cols = 32 lanes * 4).
// ---------------------------------------------------------------------------
__global__ void ln_relu_drop_kernel(const float* __restrict__ x,
                                    const float* __restrict__ mask,
                                    const float* __restrict__ gamma,
                                    const float* __restrict__ beta,
                                    int N) {
    int warp = threadIdx.x >> 5;
    int lane = threadIdx.x & 31;
    int row  = blockIdx.x * 8 + warp;
    if (row >= N) return;

    const float4 xv = reinterpret_cast<const float4*>(x)[row * 32 + lane];
    float s  = xv.x + xv.y + xv.z + xv.w;
    float ss = xv.x * xv.x + xv.y * xv.y + xv.z * xv.z + xv.w * xv.w;
#pragma unroll
    for (int o = 16; o > 0; o >>= 1) {
        s  += __shfl_xor_sync(0xFFFFFFFFu, s,  o);
        ss += __shfl_xor_sync(0xFFFFFFFFu, ss, o);
    }
    const float mu   = s * (1.0f / 128.0f);
    const float var  = ss * (1.0f / 128.0f) - mu * mu;
    const float rstd = rsqrtf(var + 1e-5f);

    const float4 g = reinterpret_cast<const float4*>(gamma)[lane];
    const float4 b = reinterpret_cast<const float4*>(beta)[lane];
    const float4 m = reinterpret_cast<const float4*>(mask)[row * 32 + lane];

    float4 hv;
    hv.x = fmaxf((xv.x - mu) * rstd * g.x + b.x, 0.0f) * m.x;
    hv.y = fmaxf((xv.y - mu) * rstd * g.y + b.y, 0.0f) * m.y;
    hv.z = fmaxf((xv.z - mu) * rstd * g.z + b.z, 0.0f) * m.z;
    hv.w = fmaxf((xv.w - mu) * rstd * g.w + b.w, 0.0f) * m.w;

    reinterpret_cast<float4*>(g_h)[row * 32 + lane]   = hv;
    reinterpret_cast<float4*>(g_agg)[row * 32 + lane] = make_float4(0.f, 0.f, 0.f, 0.f);
    if (lane == 0) g_cnt[row] = 0.0f;
}

// ---------------------------------------------------------------------------
// Kernel 2: edge scatter. One warp per edge; lane l handles float4 at col 4l.
// edge_index is int32 on device (JAX x64 disabled downcasts int64 -> int32).
// red.global.add.v4.f32 -> 4x fewer L2 atomic ops than scalar atomicAdd.
// ---------------------------------------------------------------------------
__global__ void scatter_kernel(const int* __restrict__ ei, int E) {
    int gtid = blockIdx.x * blockDim.x + threadIdx.x;
    int w    = gtid >> 5;
    int lane = gtid & 31;
    int nw   = (gridDim.x * blockDim.x) >> 5;

    for (int e = w; e < E; e += nw) {
        const int s = __ldg(&ei[e]);
        const int d = __ldg(&ei[E + e]);
        const float4 v = reinterpret_cast<const float4*>(g_h)[(size_t)s * 32 + lane];
        float* p = &g_agg[(size_t)d * 128 + lane * 4];
        asm volatile("red.global.add.v4.f32 [%0], {%1,%2,%3,%4};"
                     :: "l"(p), "f"(v.x), "f"(v.y), "f"(v.z), "f"(v.w)
                     : "memory");
        if (lane == 0) {
            asm volatile("red.global.add.f32 [%0], %1;"
                         :: "l"(&g_cnt[d]), "f"(1.0f)
                         : "memory");
        }
    }
}

// ---------------------------------------------------------------------------
// Kernel 3: fused GEMM: out = (agg/max(cnt,1)) @ W_l^T + b_l + h @ W_r^T
//         = [mean_agg | h] (Nx256) @ Wt (256x128) + b_l
// Persistent blocks: weights loaded to smem once, then loop 32-row tiles.
// 256 threads; thread (rg=tid/32, cg=tid%32) computes 4 rows x 4 cols.
// ---------------------------------------------------------------------------
__global__ void __launch_bounds__(256, 1)
gemm_kernel(const float* __restrict__ Wl, const float* __restrict__ bl,
            const float* __restrict__ Wr, float* __restrict__ out, int N) {
    extern __shared__ float sm[];
    float* Wt  = sm;                   // [256][WPITCH]
    float* ins = sm + 256 * WPITCH;    // [32][256]

    const int tid = threadIdx.x;

    // Load weights transposed: Wt[k][c] = (k<128 ? Wl[c][k] : Wr[c][k-128])
    for (int idx = tid; idx < 256 * 128; idx += 256) {
        int k = idx & 255;
        int c = idx >> 8;
        float w = (k < 128) ? Wl[c * 128 + k] : Wr[c * 128 + (k - 128)];
        Wt[k * WPITCH + c] = w;
    }

    const int cg = tid & 31;
    const int rg = tid >> 5;
    const int c0 = cg * 4;
    const int r0 = rg * 4;
    const float4 bias = *reinterpret_cast<const float4*>(&bl[c0]);

    const int ntiles = (N + 31) / 32;
    for (int tile = blockIdx.x; tile < ntiles; tile += gridDim.x) {
        __syncthreads();  // previous iteration's readers done before overwrite
        // Stage tile: ins[r][0:128] = mean_agg, ins[r][128:256] = h
        for (int i = tid; i < 32 * 64; i += 256) {
            int r = i >> 6;
            int q = i & 63;
            int grow = tile * 32 + r;
            float4 v = make_float4(0.f, 0.f, 0.f, 0.f);
            if (grow < N) {
                if (q < 32) {
                    v = reinterpret_cast<const float4*>(g_agg)[grow * 32 + q];
                    float inv = 1.0f / fmaxf(__ldg(&g_cnt[grow]), 1.0f);
                    v.x *= inv; v.y *= inv; v.z *= inv; v.w *= inv;
                } else {
                    v = reinterpret_cast<const float4*>(g_h)[grow * 32 + (q - 32)];
                }
            }
            *reinterpret_cast<float4*>(&ins[r * 256 + q * 4]) = v;
        }
        __syncthreads();

        float acc[4][4];
#pragma unroll
        for (int i = 0; i < 4; ++i)
#pragma unroll
            for (int j = 0; j < 4; ++j) acc[i][j] = 0.0f;

#pragma unroll 8
        for (int k = 0; k < 256; ++k) {
            const float4 w = *reinterpret_cast<const float4*>(&Wt[k * WPITCH + c0]);
            const float a0 = ins[(r0 + 0) * 256 + k];
            const float a1 = ins[(r0 + 1) * 256 + k];
            const float a2 = ins[(r0 + 2) * 256 + k];
            const float a3 = ins[(r0 + 3) * 256 + k];
            acc[0][0] += a0 * w.x; acc[0][1] += a0 * w.y; acc[0][2] += a0 * w.z; acc[0][3] += a0 * w.w;
            acc[1][0] += a1 * w.x; acc[1][1] += a1 * w.y; acc[1][2] += a1 * w.z; acc[1][3] += a1 * w.w;
            acc[2][0] += a2 * w.x; acc[2][1] += a2 * w.y; acc[2][2] += a2 * w.z; acc[2][3] += a2 * w.w;
            acc[3][0] += a3 * w.x; acc[3][1] += a3 * w.y; acc[3][2] += a3 * w.z; acc[3][3] += a3 * w.w;
        }

#pragma unroll
        for (int i = 0; i < 4; ++i) {
            int row = tile * 32 + r0 + i;
            if (row < N) {
                float4 o;
                o.x = acc[i][0] + bias.x;
                o.y = acc[i][1] + bias.y;
                o.z = acc[i][2] + bias.z;
                o.w = acc[i][3] + bias.w;
                reinterpret_cast<float4*>(out)[row * 32 + cg] = o;
            }
        }
    }
}

// ---------------------------------------------------------------------------
extern "C" void kernel_launch(void* const* d_in, const int* in_sizes, int n_in,
                              void* d_out, int out_size) {
    const float* x     = (const float*)d_in[0];
    const int*   eidx  = (const int*)d_in[1];   // int32: JAX default (x64 off)
    const float* mask  = (const float*)d_in[2];
    const float* gamma = (const float*)d_in[3];
    const float* beta  = (const float*)d_in[4];
    const float* Wl    = (const float*)d_in[5];
    const float* bl    = (const float*)d_in[6];
    const float* Wr    = (const float*)d_in[7];
    float*       out   = (float*)d_out;

    const int N = in_sizes[0] / D;
    const int E = in_sizes[1] / 2;

    // Kernel 1: LN + ReLU + dropout, zero agg/cnt
    ln_relu_drop_kernel<<<(N + 7) / 8, 256>>>(x, mask, gamma, beta, N);

    // Kernel 2: scatter (one warp per edge, grid-stride)
    {
        long long warps_needed = E;
        long long blocks = (warps_needed * 32 + 255) / 256;
        if (blocks > 148 * 32) blocks = 148 * 32;  // cap; grid-stride covers rest
        scatter_kernel<<<(int)blocks, 256>>>(eidx, E);
    }

    // Kernel 3: fused GEMM
    {
        int smem = (256 * WPITCH + 32 * 256) * (int)sizeof(float);
        cudaFuncSetAttribute(gemm_kernel, cudaFuncAttributeMaxDynamicSharedMemorySize, smem);
        int nsm = 148;
        cudaDeviceGetAttribute(&nsm, cudaDevAttrMultiProcessorCount, 0);
        gemm_kernel<<<nsm, 256, smem>>>(Wl, bl, Wr, out, N);
    }
}

// round 3
// speedup vs baseline: 1.0641x; 1.0641x over previous
#include <cuda_runtime.h>
#include <cstdint>

#define D 128
#define NMAX 100000

// Scratch (allocations forbidden; __device__ globals are the sanctioned path)
__device__ __align__(16) float g_h[(size_t)NMAX * D];
__device__ __align__(16) float g_agg[(size_t)NMAX * D];
__device__ float g_cnt[NMAX];

// ---------------------------------------------------------------------------
// Kernel 1: LayerNorm -> ReLU -> dropout mask; also zero agg and cnt.
// ---------------------------------------------------------------------------
__global__ void ln_relu_drop_kernel(const float* __restrict__ x,
                                    const float* __restrict__ mask,
                                    const float* __restrict__ gamma,
                                    const float* __restrict__ beta,
                                    int N) {
    int warp = threadIdx.x >> 5;
    int lane = threadIdx.x & 31;
    int row  = blockIdx.x * 8 + warp;
    if (row >= N) return;

    const float4 xv = reinterpret_cast<const float4*>(x)[row * 32 + lane];
    float s  = xv.x + xv.y + xv.z + xv.w;
    float ss = xv.x * xv.x + xv.y * xv.y + xv.z * xv.z + xv.w * xv.w;
#pragma unroll
    for (int o = 16; o > 0; o >>= 1) {
        s  += __shfl_xor_sync(0xFFFFFFFFu, s,  o);
        ss += __shfl_xor_sync(0xFFFFFFFFu, ss, o);
    }
    const float mu   = s * (1.0f / 128.0f);
    const float var  = ss * (1.0f / 128.0f) - mu * mu;
    const float rstd = rsqrtf(var + 1e-5f);

    const float4 g = reinterpret_cast<const float4*>(gamma)[lane];
    const float4 b = reinterpret_cast<const float4*>(beta)[lane];
    const float4 m = reinterpret_cast<const float4*>(mask)[row * 32 + lane];

    float4 hv;
    hv.x = fmaxf((xv.x - mu) * rstd * g.x + b.x, 0.0f) * m.x;
    hv.y = fmaxf((xv.y - mu) * rstd * g.y + b.y, 0.0f) * m.y;
    hv.z = fmaxf((xv.z - mu) * rstd * g.z + b.z, 0.0f) * m.z;
    hv.w = fmaxf((xv.w - mu) * rstd * g.w + b.w, 0.0f) * m.w;

    reinterpret_cast<float4*>(g_h)[row * 32 + lane]   = hv;
    reinterpret_cast<float4*>(g_agg)[row * 32 + lane] = make_float4(0.f, 0.f, 0.f, 0.f);
    if (lane == 0) g_cnt[row] = 0.0f;
}

// ---------------------------------------------------------------------------
// Kernel 2: edge scatter. One warp per edge; lane l handles float4 at col 4l.
// ---------------------------------------------------------------------------
__global__ void scatter_kernel(const int* __restrict__ ei, int E) {
    int gtid = blockIdx.x * blockDim.x + threadIdx.x;
    int w    = gtid >> 5;
    int lane = gtid & 31;
    int nw   = (gridDim.x * blockDim.x) >> 5;

    for (int e = w; e < E; e += nw) {
        const int s = __ldg(&ei[e]);
        const int d = __ldg(&ei[E + e]);
        const float4 v = reinterpret_cast<const float4*>(g_h)[(size_t)s * 32 + lane];
        float* p = &g_agg[(size_t)d * 128 + lane * 4];
        asm volatile("red.global.add.v4.f32 [%0], {%1,%2,%3,%4};"
                     :: "l"(p), "f"(v.x), "f"(v.y), "f"(v.z), "f"(v.w)
                     : "memory");
        if (lane == 0) {
            asm volatile("red.global.add.f32 [%0], %1;"
                         :: "l"(&g_cnt[d]), "f"(1.0f)
                         : "memory");
        }
    }
}

// ---------------------------------------------------------------------------
// Kernel 3: fused GEMM with packed fma.rn.f32x2 (FFMA2), k-paired operands.
//   out = [mean_agg | h] (Nx256) @ Wt (256x128) + b_l
// Weights transposed in smem: Wt[c][k] (k contiguous) with XOR bank swizzle
// so a thread's k-pair weight loads are 16B LDS, pair-adjacent in registers.
// Tile = 64 rows; 256 threads; thread (rg,cg) does 8 rows x 4 cols.
// ---------------------------------------------------------------------------
__global__ void __launch_bounds__(256, 1)
gemm_kernel(const float* __restrict__ Wl, const float* __restrict__ bl,
            const float* __restrict__ Wr, float* __restrict__ out, int N) {
    extern __shared__ float sm[];
    float* Wt  = sm;                 // [128 c][256 k], k-blocks XOR-swizzled
    float* ins = sm + 128 * 256;     // [64 r][256 k]

    const int tid = threadIdx.x;

    // Stage weights transposed + swizzled:
    // Wt[c][k] = (k<128 ? Wl[c*128+k] : Wr[c*128+k-128])
    // addr = c*256 + ((k>>2) ^ ((c>>2)&7))*4 + (k&3)
    for (int idx = tid; idx < 128 * 256; idx += 256) {
        int k = idx & 255;
        int c = idx >> 8;
        float w = (k < 128) ? Wl[c * 128 + k] : Wr[c * 128 + (k - 128)];
        int kb = (k >> 2) ^ ((c >> 2) & 7);
        Wt[c * 256 + kb * 4 + (k & 3)] = w;
    }

    const int cg = tid & 31;   // col group: cols 4*cg .. 4*cg+3
    const int rg = tid >> 5;   // row group: rows 8*rg .. 8*rg+7
    const int c0 = cg * 4;
    const int r0 = rg * 8;
    const int swz = cg & 7;    // (c>>2)&7 == cg for all 4 of this thread's cols
    const float4 bias = *reinterpret_cast<const float4*>(&bl[c0]);

    const int ntiles = (N + 63) / 64;
    for (int tile = blockIdx.x; tile < ntiles; tile += gridDim.x) {
        __syncthreads();  // previous iteration's readers done before overwrite
        // Stage tile: ins[r][0:128] = mean_agg, ins[r][128:256] = h
        for (int i = tid; i < 64 * 64; i += 256) {
            int r = i >> 6;
            int q = i & 63;
            int grow = tile * 64 + r;
            float4 v = make_float4(0.f, 0.f, 0.f, 0.f);
            if (grow < N) {
                if (q < 32) {
                    v = reinterpret_cast<const float4*>(g_agg)[(size_t)grow * 32 + q];
                    float inv = 1.0f / fmaxf(__ldg(&g_cnt[grow]), 1.0f);
                    v.x *= inv; v.y *= inv; v.z *= inv; v.w *= inv;
                } else {
                    v = reinterpret_cast<const float4*>(g_h)[(size_t)grow * 32 + (q - 32)];
                }
            }
            *reinterpret_cast<float4*>(&ins[r * 256 + q * 4]) = v;
        }
        __syncthreads();

        // acc[r][c] holds a k-even/k-odd partial pair packed as f32x2
        unsigned long long acc[8][4];
#pragma unroll
        for (int r = 0; r < 8; ++r)
#pragma unroll
            for (int c = 0; c < 4; ++c) acc[r][c] = 0ULL;

#pragma unroll 4
        for (int k4 = 0; k4 < 256; k4 += 4) {
            // a: broadcast 16B per row -> (a_k,a_k+1),(a_k+2,a_k+3) reg pairs
            double2 av[8];
#pragma unroll
            for (int r = 0; r < 8; ++r)
                av[r] = *reinterpret_cast<const double2*>(&ins[(r0 + r) * 256 + k4]);

#pragma unroll
            for (int cc = 0; cc < 4; ++cc) {
                const int c = c0 + cc;
                const int kbs = ((k4 >> 2) ^ swz) << 2;
                const double2 wv = *reinterpret_cast<const double2*>(&Wt[c * 256 + kbs]);
                const unsigned long long w01 = __double_as_longlong(wv.x);
                const unsigned long long w23 = __double_as_longlong(wv.y);
#pragma unroll
                for (int r = 0; r < 8; ++r) {
                    asm("fma.rn.f32x2 %0, %1, %2, %0;"
                        : "+l"(acc[r][cc])
                        : "l"(__double_as_longlong(av[r].x)), "l"(w01));
                    asm("fma.rn.f32x2 %0, %1, %2, %0;"
                        : "+l"(acc[r][cc])
                        : "l"(__double_as_longlong(av[r].y)), "l"(w23));
                }
            }
        }

#pragma unroll
        for (int r = 0; r < 8; ++r) {
            int row = tile * 64 + r0 + r;
            if (row < N) {
                float2 p0 = *reinterpret_cast<float2*>(&acc[r][0]);
                float2 p1 = *reinterpret_cast<float2*>(&acc[r][1]);
                float2 p2 = *reinterpret_cast<float2*>(&acc[r][2]);
                float2 p3 = *reinterpret_cast<float2*>(&acc[r][3]);
                float4 o;
                o.x = p0.x + p0.y + bias.x;
                o.y = p1.x + p1.y + bias.y;
                o.z = p2.x + p2.y + bias.z;
                o.w = p3.x + p3.y + bias.w;
                reinterpret_cast<float4*>(out)[(size_t)row * 32 + cg] = o;
            }
        }
    }
}

// ---------------------------------------------------------------------------
extern "C" void kernel_launch(void* const* d_in, const int* in_sizes, int n_in,
                              void* d_out, int out_size) {
    const float* x     = (const float*)d_in[0];
    const int*   eidx  = (const int*)d_in[1];   // int32 (JAX x64 disabled)
    const float* mask  = (const float*)d_in[2];
    const float* gamma = (const float*)d_in[3];
    const float* beta  = (const float*)d_in[4];
    const float* Wl    = (const float*)d_in[5];
    const float* bl    = (const float*)d_in[6];
    const float* Wr    = (const float*)d_in[7];
    float*       out   = (float*)d_out;

    const int N = in_sizes[0] / D;
    const int E = in_sizes[1] / 2;

    ln_relu_drop_kernel<<<(N + 7) / 8, 256>>>(x, mask, gamma, beta, N);

    {
        long long blocks = ((long long)E * 32 + 255) / 256;
        if (blocks > 148 * 32) blocks = 148 * 32;
        scatter_kernel<<<(int)blocks, 256>>>(eidx, E);
    }

    {
        int smem = (128 * 256 + 64 * 256) * (int)sizeof(float);  // 196.6 KB
        cudaFuncSetAttribute(gemm_kernel, cudaFuncAttributeMaxDynamicSharedMemorySize, smem);
        int nsm = 148;
        cudaDeviceGetAttribute(&nsm, cudaDevAttrMultiProcessorCount, 0);
        gemm_kernel<<<nsm, 256, smem>>>(Wl, bl, Wr, out, N);
    }
}

// round 4
// speedup vs baseline: 1.0793x; 1.0143x over previous
#include <cuda_runtime.h>
#include <cstdint>

#define D 128
#define NMAX 100000
#define EMAX 600000
#define CAP 64   // bucket capacity per dst; Poisson(6) max degree << 64

// Scratch (allocations forbidden; __device__ globals are the sanctioned path)
__device__ __align__(16) float g_h[(size_t)NMAX * D];
__device__ __align__(16) float g_agg[(size_t)NMAX * D];   // holds mean_agg
__device__ int  g_cnt_i[NMAX];
__device__ int  g_bucket[(size_t)NMAX * CAP];
__device__ int2 g_ovf_edges[EMAX];   // (src, dst) spill; safe for any input
__device__ int  g_ovf_cnt;

// ---------------------------------------------------------------------------
// Kernel 1: LayerNorm -> ReLU -> dropout; zero per-dst counters.
// ---------------------------------------------------------------------------
__global__ void ln_relu_drop_kernel(const float* __restrict__ x,
                                    const float* __restrict__ mask,
                                    const float* __restrict__ gamma,
                                    const float* __restrict__ beta,
                                    int N) {
    int warp = threadIdx.x >> 5;
    int lane = threadIdx.x & 31;
    int row  = blockIdx.x * 8 + warp;
    if (blockIdx.x == 0 && threadIdx.x == 0) g_ovf_cnt = 0;
    if (row >= N) return;

    const float4 xv = reinterpret_cast<const float4*>(x)[row * 32 + lane];
    float s  = xv.x + xv.y + xv.z + xv.w;
    float ss = xv.x * xv.x + xv.y * xv.y + xv.z * xv.z + xv.w * xv.w;
#pragma unroll
    for (int o = 16; o > 0; o >>= 1) {
        s  += __shfl_xor_sync(0xFFFFFFFFu, s,  o);
        ss += __shfl_xor_sync(0xFFFFFFFFu, ss, o);
    }
    const float mu   = s * (1.0f / 128.0f);
    const float var  = ss * (1.0f / 128.0f) - mu * mu;
    const float rstd = rsqrtf(var + 1e-5f);

    const float4 g = reinterpret_cast<const float4*>(gamma)[lane];
    const float4 b = reinterpret_cast<const float4*>(beta)[lane];
    const float4 m = reinterpret_cast<const float4*>(mask)[row * 32 + lane];

    float4 hv;
    hv.x = fmaxf((xv.x - mu) * rstd * g.x + b.x, 0.0f) * m.x;
    hv.y = fmaxf((xv.y - mu) * rstd * g.y + b.y, 0.0f) * m.y;
    hv.z = fmaxf((xv.z - mu) * rstd * g.z + b.z, 0.0f) * m.z;
    hv.w = fmaxf((xv.w - mu) * rstd * g.w + b.w, 0.0f) * m.w;

    reinterpret_cast<float4*>(g_h)[row * 32 + lane] = hv;
    if (lane == 0) g_cnt_i[row] = 0;
}

// ---------------------------------------------------------------------------
// Kernel 2a: bucket fill. One thread per edge; int atomics only.
// ---------------------------------------------------------------------------
__global__ void fill_kernel(const int* __restrict__ ei, int E) {
    int e = blockIdx.x * blockDim.x + threadIdx.x;
    if (e >= E) return;
    const int s = __ldg(&ei[e]);
    const int d = __ldg(&ei[E + e]);
    int pos = atomicAdd(&g_cnt_i[d], 1);
    if (pos < CAP) {
        g_bucket[(size_t)d * CAP + pos] = s;
    } else {
        int idx = atomicAdd(&g_ovf_cnt, 1);
        g_ovf_edges[idx] = make_int2(s, d);
    }
}

// ---------------------------------------------------------------------------
// Kernel 2b: gather-aggregate. One warp per dst row; plain loads/stores,
// writes mean directly. Spill list is empty in practice (loop skipped).
// ---------------------------------------------------------------------------
__global__ void aggregate_kernel(int N) {
    int warp = threadIdx.x >> 5;
    int lane = threadIdx.x & 31;
    int d    = blockIdx.x * 8 + warp;
    if (d >= N) return;

    const int n  = g_cnt_i[d];
    const int nb = n < CAP ? n : CAP;
    const int* bk = &g_bucket[(size_t)d * CAP];

    float4 acc = make_float4(0.f, 0.f, 0.f, 0.f);
    int j = 0;
    for (; j + 2 <= nb; j += 2) {   // unroll x2 for MLP
        int s0 = __ldg(&bk[j]);
        int s1 = __ldg(&bk[j + 1]);
        float4 v0 = reinterpret_cast<const float4*>(g_h)[(size_t)s0 * 32 + lane];
        float4 v1 = reinterpret_cast<const float4*>(g_h)[(size_t)s1 * 32 + lane];
        acc.x += v0.x + v1.x; acc.y += v0.y + v1.y;
        acc.z += v0.z + v1.z; acc.w += v0.w + v1.w;
    }
    if (j < nb) {
        int s0 = __ldg(&bk[j]);
        float4 v0 = reinterpret_cast<const float4*>(g_h)[(size_t)s0 * 32 + lane];
        acc.x += v0.x; acc.y += v0.y; acc.z += v0.z; acc.w += v0.w;
    }

    const int novf = g_ovf_cnt;     // 0 in practice
    for (int t = 0; t < novf; ++t) {
        int2 p = g_ovf_edges[t];
        if (p.y == d) {
            float4 v = reinterpret_cast<const float4*>(g_h)[(size_t)p.x * 32 + lane];
            acc.x += v.x; acc.y += v.y; acc.z += v.z; acc.w += v.w;
        }
    }

    const float inv = 1.0f / fmaxf((float)n, 1.0f);
    acc.x *= inv; acc.y *= inv; acc.z *= inv; acc.w *= inv;
    reinterpret_cast<float4*>(g_agg)[(size_t)d * 32 + lane] = acc;
}

// ---------------------------------------------------------------------------
// Kernel 3: fused GEMM with packed fma.rn.f32x2 (unchanged from R3).
//   out = [mean_agg | h] (Nx256) @ Wt (256x128) + b_l
// ---------------------------------------------------------------------------
__global__ void __launch_bounds__(256, 1)
gemm_kernel(const float* __restrict__ Wl, const float* __restrict__ bl,
            const float* __restrict__ Wr, float* __restrict__ out, int N) {
    extern __shared__ float sm[];
    float* Wt  = sm;                 // [128 c][256 k], k-blocks XOR-swizzled
    float* ins = sm + 128 * 256;     // [64 r][256 k]

    const int tid = threadIdx.x;

    for (int idx = tid; idx < 128 * 256; idx += 256) {
        int k = idx & 255;
        int c = idx >> 8;
        float w = (k < 128) ? Wl[c * 128 + k] : Wr[c * 128 + (k - 128)];
        int kb = (k >> 2) ^ ((c >> 2) & 7);
        Wt[c * 256 + kb * 4 + (k & 3)] = w;
    }

    const int cg = tid & 31;
    const int rg = tid >> 5;
    const int c0 = cg * 4;
    const int r0 = rg * 8;
    const int swz = cg & 7;
    const float4 bias = *reinterpret_cast<const float4*>(&bl[c0]);

    const int ntiles = (N + 63) / 64;
    for (int tile = blockIdx.x; tile < ntiles; tile += gridDim.x) {
        __syncthreads();
        for (int i = tid; i < 64 * 64; i += 256) {
            int r = i >> 6;
            int q = i & 63;
            int grow = tile * 64 + r;
            float4 v = make_float4(0.f, 0.f, 0.f, 0.f);
            if (grow < N) {
                v = (q < 32)
                  ? reinterpret_cast<const float4*>(g_agg)[(size_t)grow * 32 + q]
                  : reinterpret_cast<const float4*>(g_h)[(size_t)grow * 32 + (q - 32)];
            }
            *reinterpret_cast<float4*>(&ins[r * 256 + q * 4]) = v;
        }
        __syncthreads();

        unsigned long long acc[8][4];
#pragma unroll
        for (int r = 0; r < 8; ++r)
#pragma unroll
            for (int c = 0; c < 4; ++c) acc[r][c] = 0ULL;

#pragma unroll 4
        for (int k4 = 0; k4 < 256; k4 += 4) {
            double2 av[8];
#pragma unroll
            for (int r = 0; r < 8; ++r)
                av[r] = *reinterpret_cast<const double2*>(&ins[(r0 + r) * 256 + k4]);

#pragma unroll
            for (int cc = 0; cc < 4; ++cc) {
                const int c = c0 + cc;
                const int kbs = ((k4 >> 2) ^ swz) << 2;
                const double2 wv = *reinterpret_cast<const double2*>(&Wt[c * 256 + kbs]);
                const unsigned long long w01 = __double_as_longlong(wv.x);
                const unsigned long long w23 = __double_as_longlong(wv.y);
#pragma unroll
                for (int r = 0; r < 8; ++r) {
                    asm("fma.rn.f32x2 %0, %1, %2, %0;"
                        : "+l"(acc[r][cc])
                        : "l"(__double_as_longlong(av[r].x)), "l"(w01));
                    asm("fma.rn.f32x2 %0, %1, %2, %0;"
                        : "+l"(acc[r][cc])
                        : "l"(__double_as_longlong(av[r].y)), "l"(w23));
                }
            }
        }

#pragma unroll
        for (int r = 0; r < 8; ++r) {
            int row = tile * 64 + r0 + r;
            if (row < N) {
                float2 p0 = *reinterpret_cast<float2*>(&acc[r][0]);
                float2 p1 = *reinterpret_cast<float2*>(&acc[r][1]);
                float2 p2 = *reinterpret_cast<float2*>(&acc[r][2]);
                float2 p3 = *reinterpret_cast<float2*>(&acc[r][3]);
                float4 o;
                o.x = p0.x + p0.y + bias.x;
                o.y = p1.x + p1.y + bias.y;
                o.z = p2.x + p2.y + bias.z;
                o.w = p3.x + p3.y + bias.w;
                reinterpret_cast<float4*>(out)[(size_t)row * 32 + cg] = o;
            }
        }
    }
}

// ---------------------------------------------------------------------------
extern "C" void kernel_launch(void* const* d_in, const int* in_sizes, int n_in,
                              void* d_out, int out_size) {
    const float* x     = (const float*)d_in[0];
    const int*   eidx  = (const int*)d_in[1];   // int32 (JAX x64 disabled)
    const float* mask  = (const float*)d_in[2];
    const float* gamma = (const float*)d_in[3];
    const float* beta  = (const float*)d_in[4];
    const float* Wl    = (const float*)d_in[5];
    const float* bl    = (const float*)d_in[6];
    const float* Wr    = (const float*)d_in[7];
    float*       out   = (float*)d_out;

    const int N = in_sizes[0] / D;
    const int E = in_sizes[1] / 2;

    ln_relu_drop_kernel<<<(N + 7) / 8, 256>>>(x, mask, gamma, beta, N);
    fill_kernel<<<(E + 255) / 256, 256>>>(eidx, E);
    aggregate_kernel<<<(N + 7) / 8, 256>>>(N);

    {
        int smem = (128 * 256 + 64 * 256) * (int)sizeof(float);  // 196.6 KB
        cudaFuncSetAttribute(gemm_kernel, cudaFuncAttributeMaxDynamicSharedMemorySize, smem);
        int nsm = 148;
        cudaDeviceGetAttribute(&nsm, cudaDevAttrMultiProcessorCount, 0);
        gemm_kernel<<<nsm, 256, smem>>>(Wl, bl, Wr, out, N);
    }
}

// round 6
// speedup vs baseline: 1.4835x; 1.3745x over previous
#include <cuda_runtime.h>
#include <cstdint>

#define D 128
#define NMAX 100000
#define EMAX 600000
#define CAP 64
#define PITCH 260   // 260 % 32 == 4 -> fragment rows hit distinct banks

// Scratch
__device__ __align__(16) float g_h[(size_t)NMAX * D];
__device__ __align__(16) float g_agg[(size_t)NMAX * D];   // mean_agg
__device__ int  g_cnt_i[NMAX];
__device__ int  g_bucket[(size_t)NMAX * CAP];
__device__ int2 g_ovf_edges[EMAX];
__device__ int  g_ovf_cnt;

__device__ __forceinline__ float f2tf32f(float f) {
    uint32_t t;
    asm("cvt.rna.tf32.f32 %0, %1;" : "=r"(t) : "f"(f));
    return __uint_as_float(t);
}

// ---------------------------------------------------------------------------
// Kernel 1: LayerNorm -> ReLU -> dropout; zero per-dst counters.
// ---------------------------------------------------------------------------
__global__ void ln_relu_drop_kernel(const float* __restrict__ x,
                                    const float* __restrict__ mask,
                                    const float* __restrict__ gamma,
                                    const float* __restrict__ beta,
                                    int N) {
    int warp = threadIdx.x >> 5;
    int lane = threadIdx.x & 31;
    int row  = blockIdx.x * 8 + warp;
    if (blockIdx.x == 0 && threadIdx.x == 0) g_ovf_cnt = 0;
    if (row >= N) return;

    const float4 xv = reinterpret_cast<const float4*>(x)[row * 32 + lane];
    float s  = xv.x + xv.y + xv.z + xv.w;
    float ss = xv.x * xv.x + xv.y * xv.y + xv.z * xv.z + xv.w * xv.w;
#pragma unroll
    for (int o = 16; o > 0; o >>= 1) {
        s  += __shfl_xor_sync(0xFFFFFFFFu, s,  o);
        ss += __shfl_xor_sync(0xFFFFFFFFu, ss, o);
    }
    const float mu   = s * (1.0f / 128.0f);
    const float var  = ss * (1.0f / 128.0f) - mu * mu;
    const float rstd = rsqrtf(var + 1e-5f);

    const float4 g = reinterpret_cast<const float4*>(gamma)[lane];
    const float4 b = reinterpret_cast<const float4*>(beta)[lane];
    const float4 m = reinterpret_cast<const float4*>(mask)[row * 32 + lane];

    float4 hv;
    hv.x = fmaxf((xv.x - mu) * rstd * g.x + b.x, 0.0f) * m.x;
    hv.y = fmaxf((xv.y - mu) * rstd * g.y + b.y, 0.0f) * m.y;
    hv.z = fmaxf((xv.z - mu) * rstd * g.z + b.z, 0.0f) * m.z;
    hv.w = fmaxf((xv.w - mu) * rstd * g.w + b.w, 0.0f) * m.w;

    reinterpret_cast<float4*>(g_h)[row * 32 + lane] = hv;
    if (lane == 0) g_cnt_i[row] = 0;
}

// ---------------------------------------------------------------------------
// Kernel 2a: bucket fill (int atomics only).
// ---------------------------------------------------------------------------
__global__ void fill_kernel(const int* __restrict__ ei, int E) {
    int e = blockIdx.x * blockDim.x + threadIdx.x;
    if (e >= E) return;
    const int s = __ldg(&ei[e]);
    const int d = __ldg(&ei[E + e]);
    int pos = atomicAdd(&g_cnt_i[d], 1);
    if (pos < CAP) g_bucket[(size_t)d * CAP + pos] = s;
    else {
        int idx = atomicAdd(&g_ovf_cnt, 1);
        g_ovf_edges[idx] = make_int2(s, d);
    }
}

// ---------------------------------------------------------------------------
// Kernel 2b: gather-aggregate; writes mean directly.
// ---------------------------------------------------------------------------
__global__ void aggregate_kernel(int N) {
    int warp = threadIdx.x >> 5;
    int lane = threadIdx.x & 31;
    int d    = blockIdx.x * 8 + warp;
    if (d >= N) return;

    const int n  = g_cnt_i[d];
    const int nb = n < CAP ? n : CAP;
    const int* bk = &g_bucket[(size_t)d * CAP];

    float4 acc = make_float4(0.f, 0.f, 0.f, 0.f);
    int j = 0;
    for (; j + 2 <= nb; j += 2) {
        int s0 = __ldg(&bk[j]);
        int s1 = __ldg(&bk[j + 1]);
        float4 v0 = reinterpret_cast<const float4*>(g_h)[(size_t)s0 * 32 + lane];
        float4 v1 = reinterpret_cast<const float4*>(g_h)[(size_t)s1 * 32 + lane];
        acc.x += v0.x + v1.x; acc.y += v0.y + v1.y;
        acc.z += v0.z + v1.z; acc.w += v0.w + v1.w;
    }
    if (j < nb) {
        int s0 = __ldg(&bk[j]);
        float4 v0 = reinterpret_cast<const float4*>(g_h)[(size_t)s0 * 32 + lane];
        acc.x += v0.x; acc.y += v0.y; acc.z += v0.z; acc.w += v0.w;
    }
    const int novf = g_ovf_cnt;
    for (int t = 0; t < novf; ++t) {
        int2 p = g_ovf_edges[t];
        if (p.y == d) {
            float4 v = reinterpret_cast<const float4*>(g_h)[(size_t)p.x * 32 + lane];
            acc.x += v.x; acc.y += v.y; acc.z += v.z; acc.w += v.w;
        }
    }
    const float inv = 1.0f / fmaxf((float)n, 1.0f);
    acc.x *= inv; acc.y *= inv; acc.z *= inv; acc.w *= inv;
    reinterpret_cast<float4*>(g_agg)[(size_t)d * 32 + lane] = acc;
}

// ---------------------------------------------------------------------------
// Kernel 3: tf32 mma.sync GEMM.  out = [mean_agg|h] (Nx256) @ Wcat^T + b_l.
// Block tile M=64, N=128, K=256.  8 warps = 2 row-groups(32r) x 4 col-groups(32c).
// Per warp: 2 mblk(m16) x 4 nblk(n8), k in 32 steps of 8.
// smem: Wt[128][PITCH] tf32 (staged once/block) + ins[64][PITCH] tf32.
// ---------------------------------------------------------------------------
__global__ void __launch_bounds__(256, 1)
gemm_mma_kernel(const float* __restrict__ Wl, const float* __restrict__ bl,
                const float* __restrict__ Wr, float* __restrict__ out, int N) {
    extern __shared__ float sm[];
    float* Wt  = sm;                   // [128][PITCH]
    float* ins = sm + 128 * PITCH;     // [64][PITCH]

    const int tid  = threadIdx.x;
    const int lane = tid & 31;
    const int wid  = tid >> 5;
    const int g    = lane >> 2;        // fragment row group 0..7
    const int t    = lane & 3;         // fragment k sub 0..3
    const int wr   = wid >> 2;         // 0..1: rows wr*32
    const int wc   = wid & 3;          // 0..3: cols wc*32
    const int r0   = wr * 32;
    const int c0   = wc * 32;

    // Stage weights (tf32-rounded): Wt[n][k] = k<128 ? Wl[n][k] : Wr[n][k-128]
    for (int idx = tid; idx < 128 * 256; idx += 256) {
        int n = idx >> 8;
        int k = idx & 255;
        float w = (k < 128) ? Wl[n * 128 + k] : Wr[n * 128 + (k - 128)];
        Wt[n * PITCH + k] = f2tf32f(w);
    }

    // Per-thread constant bias for epilogue: cols c0 + n*8 + 2t, +1
    float2 bias[4];
#pragma unroll
    for (int n = 0; n < 4; ++n) {
        int col = c0 + n * 8 + 2 * t;
        bias[n].x = __ldg(&bl[col]);
        bias[n].y = __ldg(&bl[col + 1]);
    }

    const float* Abase = ins + (r0 + g) * PITCH + t;
    const float* Bbase = Wt  + (c0 + g) * PITCH + t;

    const int ntiles = (N + 63) / 64;
    for (int tile = blockIdx.x; tile < ntiles; tile += gridDim.x) {
        __syncthreads();
        // Stage tile rows (tf32-rounded): ins[r][0:128]=mean_agg, [128:256]=h
        for (int i = tid; i < 64 * 64; i += 256) {
            int r = i >> 6;
            int q = i & 63;
            int grow = tile * 64 + r;
            float4 v = make_float4(0.f, 0.f, 0.f, 0.f);
            if (grow < N) {
                v = (q < 32)
                  ? reinterpret_cast<const float4*>(g_agg)[(size_t)grow * 32 + q]
                  : reinterpret_cast<const float4*>(g_h)[(size_t)grow * 32 + (q - 32)];
            }
            float4 tv;
            tv.x = f2tf32f(v.x); tv.y = f2tf32f(v.y);
            tv.z = f2tf32f(v.z); tv.w = f2tf32f(v.w);
            *reinterpret_cast<float4*>(&ins[r * PITCH + q * 4]) = tv;
        }
        __syncthreads();

        float acc[2][4][4];
#pragma unroll
        for (int m = 0; m < 2; ++m)
#pragma unroll
            for (int n = 0; n < 4; ++n)
#pragma unroll
                for (int i = 0; i < 4; ++i) acc[m][n][i] = 0.0f;

#pragma unroll 4
        for (int ks = 0; ks < 32; ++ks) {
            const float* ap = Abase + ks * 8;
            const float* bp = Bbase + ks * 8;

            uint32_t a[2][4];
#pragma unroll
            for (int m = 0; m < 2; ++m) {
                const float* p = ap + m * 16 * PITCH;
                a[m][0] = __float_as_uint(p[0]);
                a[m][1] = __float_as_uint(p[8 * PITCH]);
                a[m][2] = __float_as_uint(p[4]);
                a[m][3] = __float_as_uint(p[8 * PITCH + 4]);
            }
            uint32_t b[4][2];
#pragma unroll
            for (int n = 0; n < 4; ++n) {
                const float* p = bp + n * 8 * PITCH;
                b[n][0] = __float_as_uint(p[0]);
                b[n][1] = __float_as_uint(p[4]);
            }
#pragma unroll
            for (int m = 0; m < 2; ++m)
#pragma unroll
                for (int n = 0; n < 4; ++n) {
                    asm("mma.sync.aligned.m16n8k8.row.col.f32.tf32.tf32.f32 "
                        "{%0,%1,%2,%3}, {%4,%5,%6,%7}, {%8,%9}, {%0,%1,%2,%3};"
                        : "+f"(acc[m][n][0]), "+f"(acc[m][n][1]),
                          "+f"(acc[m][n][2]), "+f"(acc[m][n][3])
                        : "r"(a[m][0]), "r"(a[m][1]), "r"(a[m][2]), "r"(a[m][3]),
                          "r"(b[n][0]), "r"(b[n][1]));
                }
        }

        // Epilogue: acc rows {g, g+8} per mblk, cols c0+n*8+2t (+1)
#pragma unroll
        for (int m = 0; m < 2; ++m) {
            int row0 = tile * 64 + r0 + m * 16 + g;
            int row1 = row0 + 8;
#pragma unroll
            for (int n = 0; n < 4; ++n) {
                int colh = (c0 + n * 8 + 2 * t) >> 1;
                if (row0 < N) {
                    float2 o0 = make_float2(acc[m][n][0] + bias[n].x,
                                            acc[m][n][1] + bias[n].y);
                    reinterpret_cast<float2*>(out)[(size_t)row0 * 64 + colh] = o0;
                }
                if (row1 < N) {
                    float2 o1 = make_float2(acc[m][n][2] + bias[n].x,
                                            acc[m][n][3] + bias[n].y);
                    reinterpret_cast<float2*>(out)[(size_t)row1 * 64 + colh] = o1;
                }
            }
        }
    }
}

// ---------------------------------------------------------------------------
extern "C" void kernel_launch(void* const* d_in, const int* in_sizes, int n_in,
                              void* d_out, int out_size) {
    const float* x     = (const float*)d_in[0];
    const int*   eidx  = (const int*)d_in[1];   // int32 (JAX x64 disabled)
    const float* mask  = (const float*)d_in[2];
    const float* gamma = (const float*)d_in[3];
    const float* beta  = (const float*)d_in[4];
    const float* Wl    = (const float*)d_in[5];
    const float* bl    = (const float*)d_in[6];
    const float* Wr    = (const float*)d_in[7];
    float*       out   = (float*)d_out;

    const int N = in_sizes[0] / D;
    const int E = in_sizes[1] / 2;

    ln_relu_drop_kernel<<<(N + 7) / 8, 256>>>(x, mask, gamma, beta, N);
    fill_kernel<<<(E + 255) / 256, 256>>>(eidx, E);
    aggregate_kernel<<<(N + 7) / 8, 256>>>(N);

    {
        int smem = (128 * PITCH + 64 * PITCH) * (int)sizeof(float);  // 199,680 B
        cudaFuncSetAttribute(gemm_mma_kernel, cudaFuncAttributeMaxDynamicSharedMemorySize, smem);
        int nsm = 148;
        cudaDeviceGetAttribute(&nsm, cudaDevAttrMultiProcessorCount, 0);
        gemm_mma_kernel<<<nsm, 256, smem>>>(Wl, bl, Wr, out, N);
    }
}

// round 7
// speedup vs baseline: 1.8396x; 1.2400x over previous
#include <cuda_runtime.h>
#include <cstdint>

#define D 128
#define NMAX 100000
#define EMAX 600000
#define CAP 64
#define PITCH 260   // %32==4 -> stride-PITCH rows hit distinct banks; 16B rows

// Scratch
__device__ __align__(16) float g_h[(size_t)NMAX * D];
__device__ __align__(16) float g_agg[(size_t)NMAX * D];   // mean_agg
__device__ int  g_cnt_i[NMAX];
__device__ int  g_bucket[(size_t)NMAX * CAP];
__device__ int2 g_ovf_edges[EMAX];
__device__ int  g_ovf_cnt;

__device__ __forceinline__ float f2tf32f(float f) {
    uint32_t t;
    asm("cvt.rna.tf32.f32 %0, %1;" : "=r"(t) : "f"(f));
    return __uint_as_float(t);
}

// ---------------------------------------------------------------------------
// Kernel 1: LayerNorm -> ReLU -> dropout; zero per-dst counters.
// ---------------------------------------------------------------------------
__global__ void ln_relu_drop_kernel(const float* __restrict__ x,
                                    const float* __restrict__ mask,
                                    const float* __restrict__ gamma,
                                    const float* __restrict__ beta,
                                    int N) {
    int warp = threadIdx.x >> 5;
    int lane = threadIdx.x & 31;
    int row  = blockIdx.x * 8 + warp;
    if (blockIdx.x == 0 && threadIdx.x == 0) g_ovf_cnt = 0;
    if (row >= N) return;

    const float4 xv = reinterpret_cast<const float4*>(x)[row * 32 + lane];
    float s  = xv.x + xv.y + xv.z + xv.w;
    float ss = xv.x * xv.x + xv.y * xv.y + xv.z * xv.z + xv.w * xv.w;
#pragma unroll
    for (int o = 16; o > 0; o >>= 1) {
        s  += __shfl_xor_sync(0xFFFFFFFFu, s,  o);
        ss += __shfl_xor_sync(0xFFFFFFFFu, ss, o);
    }
    const float mu   = s * (1.0f / 128.0f);
    const float var  = ss * (1.0f / 128.0f) - mu * mu;
    const float rstd = rsqrtf(var + 1e-5f);

    const float4 g = reinterpret_cast<const float4*>(gamma)[lane];
    const float4 b = reinterpret_cast<const float4*>(beta)[lane];
    const float4 m = reinterpret_cast<const float4*>(mask)[row * 32 + lane];

    float4 hv;
    hv.x = fmaxf((xv.x - mu) * rstd * g.x + b.x, 0.0f) * m.x;
    hv.y = fmaxf((xv.y - mu) * rstd * g.y + b.y, 0.0f) * m.y;
    hv.z = fmaxf((xv.z - mu) * rstd * g.z + b.z, 0.0f) * m.z;
    hv.w = fmaxf((xv.w - mu) * rstd * g.w + b.w, 0.0f) * m.w;

    reinterpret_cast<float4*>(g_h)[row * 32 + lane] = hv;
    if (lane == 0) g_cnt_i[row] = 0;
}

// ---------------------------------------------------------------------------
// Kernel 2a: bucket fill (int atomics only).
// ---------------------------------------------------------------------------
__global__ void fill_kernel(const int* __restrict__ ei, int E) {
    int e = blockIdx.x * blockDim.x + threadIdx.x;
    if (e >= E) return;
    const int s = __ldg(&ei[e]);
    const int d = __ldg(&ei[E + e]);
    int pos = atomicAdd(&g_cnt_i[d], 1);
    if (pos < CAP) g_bucket[(size_t)d * CAP + pos] = s;
    else {
        int idx = atomicAdd(&g_ovf_cnt, 1);
        g_ovf_edges[idx] = make_int2(s, d);
    }
}

// ---------------------------------------------------------------------------
// Kernel 2b: gather-aggregate; writes mean directly.
// ---------------------------------------------------------------------------
__global__ void aggregate_kernel(int N) {
    int warp = threadIdx.x >> 5;
    int lane = threadIdx.x & 31;
    int d    = blockIdx.x * 8 + warp;
    if (d >= N) return;

    const int n  = g_cnt_i[d];
    const int nb = n < CAP ? n : CAP;
    const int* bk = &g_bucket[(size_t)d * CAP];

    float4 acc = make_float4(0.f, 0.f, 0.f, 0.f);
    int j = 0;
    for (; j + 2 <= nb; j += 2) {
        int s0 = __ldg(&bk[j]);
        int s1 = __ldg(&bk[j + 1]);
        float4 v0 = reinterpret_cast<const float4*>(g_h)[(size_t)s0 * 32 + lane];
        float4 v1 = reinterpret_cast<const float4*>(g_h)[(size_t)s1 * 32 + lane];
        acc.x += v0.x + v1.x; acc.y += v0.y + v1.y;
        acc.z += v0.z + v1.z; acc.w += v0.w + v1.w;
    }
    if (j < nb) {
        int s0 = __ldg(&bk[j]);
        float4 v0 = reinterpret_cast<const float4*>(g_h)[(size_t)s0 * 32 + lane];
        acc.x += v0.x; acc.y += v0.y; acc.z += v0.z; acc.w += v0.w;
    }
    const int novf = g_ovf_cnt;
    for (int t = 0; t < novf; ++t) {
        int2 p = g_ovf_edges[t];
        if (p.y == d) {
            float4 v = reinterpret_cast<const float4*>(g_h)[(size_t)p.x * 32 + lane];
            acc.x += v.x; acc.y += v.y; acc.z += v.z; acc.w += v.w;
        }
    }
    const float inv = 1.0f / fmaxf((float)n, 1.0f);
    acc.x *= inv; acc.y *= inv; acc.z *= inv; acc.w *= inv;
    reinterpret_cast<float4*>(g_agg)[(size_t)d * 32 + lane] = acc;
}

// ---------------------------------------------------------------------------
// Kernel 3: tf32 mma.sync GEMM.  out = [mean_agg|h] (Nx256) @ Wcat^T + b_l.
// Block tile M=64, N=128, K=256.  512 threads = 16 warps:
//   2 row-groups (32 rows) x 8 col-groups (16 cols); warp = 2 mblk x 2 nblk.
// smem: Wt[128][PITCH] tf32 (staged once/block) + ins[64][PITCH] tf32.
// ---------------------------------------------------------------------------
__global__ void __launch_bounds__(512, 1)
gemm_mma_kernel(const float* __restrict__ Wl, const float* __restrict__ bl,
                const float* __restrict__ Wr, float* __restrict__ out, int N) {
    extern __shared__ float sm[];
    float* Wt  = sm;                   // [128][PITCH]
    float* ins = sm + 128 * PITCH;     // [64][PITCH]

    const int tid  = threadIdx.x;
    const int lane = tid & 31;
    const int wid  = tid >> 5;
    const int g    = lane >> 2;        // fragment row 0..7
    const int t    = lane & 3;         // fragment k sub 0..3
    const int wr   = wid >> 3;         // 0..1: rows wr*32
    const int wc   = wid & 7;          // 0..7: cols wc*16
    const int r0   = wr * 32;
    const int c0   = wc * 16;

    // Stage weights (tf32-rounded): Wt[n][k] = k<128 ? Wl[n][k] : Wr[n][k-128]
    for (int idx = tid; idx < 128 * 256; idx += 512) {
        int n = idx >> 8;
        int k = idx & 255;
        float w = (k < 128) ? Wl[n * 128 + k] : Wr[n * 128 + (k - 128)];
        Wt[n * PITCH + k] = f2tf32f(w);
    }

    // Per-thread bias for epilogue: cols c0 + n*8 + 2t, +1
    float2 bias[2];
#pragma unroll
    for (int n = 0; n < 2; ++n) {
        int col = c0 + n * 8 + 2 * t;
        bias[n].x = __ldg(&bl[col]);
        bias[n].y = __ldg(&bl[col + 1]);
    }

    const float* Abase = ins + (r0 + g) * PITCH + t;
    const float* Bbase = Wt  + (c0 + g) * PITCH + t;

    const int ntiles = (N + 63) / 64;
    for (int tile = blockIdx.x; tile < ntiles; tile += gridDim.x) {
        __syncthreads();
        // Stage tile rows (tf32-rounded): ins[r][0:128]=mean_agg, [128:256]=h
        for (int i = tid; i < 64 * 64; i += 512) {
            int r = i >> 6;
            int q = i & 63;
            int grow = tile * 64 + r;
            float4 v = make_float4(0.f, 0.f, 0.f, 0.f);
            if (grow < N) {
                v = (q < 32)
                  ? reinterpret_cast<const float4*>(g_agg)[(size_t)grow * 32 + q]
                  : reinterpret_cast<const float4*>(g_h)[(size_t)grow * 32 + (q - 32)];
            }
            float4 tv;
            tv.x = f2tf32f(v.x); tv.y = f2tf32f(v.y);
            tv.z = f2tf32f(v.z); tv.w = f2tf32f(v.w);
            *reinterpret_cast<float4*>(&ins[r * PITCH + q * 4]) = tv;
        }
        __syncthreads();

        float acc[2][2][4];
#pragma unroll
        for (int m = 0; m < 2; ++m)
#pragma unroll
            for (int n = 0; n < 2; ++n)
#pragma unroll
                for (int i = 0; i < 4; ++i) acc[m][n][i] = 0.0f;

#pragma unroll 8
        for (int ks = 0; ks < 32; ++ks) {
            const float* ap = Abase + ks * 8;
            const float* bp = Bbase + ks * 8;

            uint32_t a[2][4];
#pragma unroll
            for (int m = 0; m < 2; ++m) {
                const float* p = ap + m * 16 * PITCH;
                a[m][0] = __float_as_uint(p[0]);
                a[m][1] = __float_as_uint(p[8 * PITCH]);
                a[m][2] = __float_as_uint(p[4]);
                a[m][3] = __float_as_uint(p[8 * PITCH + 4]);
            }
            uint32_t b[2][2];
#pragma unroll
            for (int n = 0; n < 2; ++n) {
                const float* p = bp + n * 8 * PITCH;
                b[n][0] = __float_as_uint(p[0]);
                b[n][1] = __float_as_uint(p[4]);
            }
#pragma unroll
            for (int m = 0; m < 2; ++m)
#pragma unroll
                for (int n = 0; n < 2; ++n) {
                    asm("mma.sync.aligned.m16n8k8.row.col.f32.tf32.tf32.f32 "
                        "{%0,%1,%2,%3}, {%4,%5,%6,%7}, {%8,%9}, {%0,%1,%2,%3};"
                        : "+f"(acc[m][n][0]), "+f"(acc[m][n][1]),
                          "+f"(acc[m][n][2]), "+f"(acc[m][n][3])
                        : "r"(a[m][0]), "r"(a[m][1]), "r"(a[m][2]), "r"(a[m][3]),
                          "r"(b[n][0]), "r"(b[n][1]));
                }
        }

        // Epilogue: rows {g, g+8} per mblk, cols c0+n*8+2t (+1)
#pragma unroll
        for (int m = 0; m < 2; ++m) {
            int row0 = tile * 64 + r0 + m * 16 + g;
            int row1 = row0 + 8;
#pragma unroll
            for (int n = 0; n < 2; ++n) {
                int colh = (c0 + n * 8 + 2 * t) >> 1;
                if (row0 < N) {
                    float2 o0 = make_float2(acc[m][n][0] + bias[n].x,
                                            acc[m][n][1] + bias[n].y);
                    reinterpret_cast<float2*>(out)[(size_t)row0 * 64 + colh] = o0;
                }
                if (row1 < N) {
                    float2 o1 = make_float2(acc[m][n][2] + bias[n].x,
                                            acc[m][n][3] + bias[n].y);
                    reinterpret_cast<float2*>(out)[(size_t)row1 * 64 + colh] = o1;
                }
            }
        }
    }
}

// ---------------------------------------------------------------------------
extern "C" void kernel_launch(void* const* d_in, const int* in_sizes, int n_in,
                              void* d_out, int out_size) {
    const float* x     = (const float*)d_in[0];
    const int*   eidx  = (const int*)d_in[1];   // int32 (JAX x64 disabled)
    const float* mask  = (const float*)d_in[2];
    const float* gamma = (const float*)d_in[3];
    const float* beta  = (const float*)d_in[4];
    const float* Wl    = (const float*)d_in[5];
    const float* bl    = (const float*)d_in[6];
    const float* Wr    = (const float*)d_in[7];
    float*       out   = (float*)d_out;

    const int N = in_sizes[0] / D;
    const int E = in_sizes[1] / 2;

    ln_relu_drop_kernel<<<(N + 7) / 8, 256>>>(x, mask, gamma, beta, N);
    fill_kernel<<<(E + 255) / 256, 256>>>(eidx, E);
    aggregate_kernel<<<(N + 7) / 8, 256>>>(N);

    {
        int smem = (128 * PITCH + 64 * PITCH) * (int)sizeof(float);  // 199,680 B
        cudaFuncSetAttribute(gemm_mma_kernel, cudaFuncAttributeMaxDynamicSharedMemorySize, smem);
        int nsm = 148;
        cudaDeviceGetAttribute(&nsm, cudaDevAttrMultiProcessorCount, 0);
        gemm_mma_kernel<<<nsm, 512, smem>>>(Wl, bl, Wr, out, N);
    }
}

// round 8
// speedup vs baseline: 1.9733x; 1.0727x over previous
#include <cuda_runtime.h>
#include <cstdint>

#define D 128
#define NMAX 100000
#define EMAX 600000
#define CAP 64
#define PITCH 260   // %32==4 -> fragment rows hit distinct banks; 16B-aligned rows

// Scratch
__device__ __align__(16) float g_h[(size_t)NMAX * D];
__device__ __align__(16) float g_agg[(size_t)NMAX * D];   // mean_agg
__device__ int  g_cnt_i[NMAX];
__device__ int  g_bucket[(size_t)NMAX * CAP];
__device__ int2 g_ovf_edges[EMAX];
__device__ int  g_ovf_cnt;

__device__ __forceinline__ float f2tf32f(float f) {
    uint32_t t;
    asm("cvt.rna.tf32.f32 %0, %1;" : "=r"(t) : "f"(f));
    return __uint_as_float(t);
}

// ---------------------------------------------------------------------------
// Kernel 1: LayerNorm -> ReLU -> dropout; zero per-dst counters.
// ---------------------------------------------------------------------------
__global__ void ln_relu_drop_kernel(const float* __restrict__ x,
                                    const float* __restrict__ mask,
                                    const float* __restrict__ gamma,
                                    const float* __restrict__ beta,
                                    int N) {
    int warp = threadIdx.x >> 5;
    int lane = threadIdx.x & 31;
    int row  = blockIdx.x * 8 + warp;
    if (blockIdx.x == 0 && threadIdx.x == 0) g_ovf_cnt = 0;
    if (row >= N) return;

    const float4 xv = reinterpret_cast<const float4*>(x)[row * 32 + lane];
    float s  = xv.x + xv.y + xv.z + xv.w;
    float ss = xv.x * xv.x + xv.y * xv.y + xv.z * xv.z + xv.w * xv.w;
#pragma unroll
    for (int o = 16; o > 0; o >>= 1) {
        s  += __shfl_xor_sync(0xFFFFFFFFu, s,  o);
        ss += __shfl_xor_sync(0xFFFFFFFFu, ss, o);
    }
    const float mu   = s * (1.0f / 128.0f);
    const float var  = ss * (1.0f / 128.0f) - mu * mu;
    const float rstd = rsqrtf(var + 1e-5f);

    const float4 g = reinterpret_cast<const float4*>(gamma)[lane];
    const float4 b = reinterpret_cast<const float4*>(beta)[lane];
    const float4 m = reinterpret_cast<const float4*>(mask)[row * 32 + lane];

    float4 hv;
    hv.x = fmaxf((xv.x - mu) * rstd * g.x + b.x, 0.0f) * m.x;
    hv.y = fmaxf((xv.y - mu) * rstd * g.y + b.y, 0.0f) * m.y;
    hv.z = fmaxf((xv.z - mu) * rstd * g.z + b.z, 0.0f) * m.z;
    hv.w = fmaxf((xv.w - mu) * rstd * g.w + b.w, 0.0f) * m.w;

    reinterpret_cast<float4*>(g_h)[row * 32 + lane] = hv;
    if (lane == 0) g_cnt_i[row] = 0;
}

// ---------------------------------------------------------------------------
// Kernel 2a: bucket fill (int atomics only).
// ---------------------------------------------------------------------------
__global__ void fill_kernel(const int* __restrict__ ei, int E) {
    int e = blockIdx.x * blockDim.x + threadIdx.x;
    if (e >= E) return;
    const int s = __ldg(&ei[e]);
    const int d = __ldg(&ei[E + e]);
    int pos = atomicAdd(&g_cnt_i[d], 1);
    if (pos < CAP) g_bucket[(size_t)d * CAP + pos] = s;
    else {
        int idx = atomicAdd(&g_ovf_cnt, 1);
        g_ovf_edges[idx] = make_int2(s, d);
    }
}

// ---------------------------------------------------------------------------
// Kernel 2b: gather-aggregate; writes mean directly.
// ---------------------------------------------------------------------------
__global__ void aggregate_kernel(int N) {
    int warp = threadIdx.x >> 5;
    int lane = threadIdx.x & 31;
    int d    = blockIdx.x * 8 + warp;
    if (d >= N) return;

    const int n  = g_cnt_i[d];
    const int nb = n < CAP ? n : CAP;
    const int* bk = &g_bucket[(size_t)d * CAP];

    float4 acc = make_float4(0.f, 0.f, 0.f, 0.f);
    int j = 0;
    for (; j + 2 <= nb; j += 2) {
        int s0 = __ldg(&bk[j]);
        int s1 = __ldg(&bk[j + 1]);
        float4 v0 = reinterpret_cast<const float4*>(g_h)[(size_t)s0 * 32 + lane];
        float4 v1 = reinterpret_cast<const float4*>(g_h)[(size_t)s1 * 32 + lane];
        acc.x += v0.x + v1.x; acc.y += v0.y + v1.y;
        acc.z += v0.z + v1.z; acc.w += v0.w + v1.w;
    }
    if (j < nb) {
        int s0 = __ldg(&bk[j]);
        float4 v0 = reinterpret_cast<const float4*>(g_h)[(size_t)s0 * 32 + lane];
        acc.x += v0.x; acc.y += v0.y; acc.z += v0.z; acc.w += v0.w;
    }
    const int novf = g_ovf_cnt;
    for (int t = 0; t < novf; ++t) {
        int2 p = g_ovf_edges[t];
        if (p.y == d) {
            float4 v = reinterpret_cast<const float4*>(g_h)[(size_t)p.x * 32 + lane];
            acc.x += v.x; acc.y += v.y; acc.z += v.z; acc.w += v.w;
        }
    }
    const float inv = 1.0f / fmaxf((float)n, 1.0f);
    acc.x *= inv; acc.y *= inv; acc.z *= inv; acc.w *= inv;
    reinterpret_cast<float4*>(g_agg)[(size_t)d * 32 + lane] = acc;
}

// ---------------------------------------------------------------------------
// Kernel 3: tf32 mma.sync GEMM.  out = [mean_agg|h] (Nx256) @ Wcat^T + b_l.
// Block tile M=64, N=128, K=256.  1024 threads = 32 warps:
//   4 row-groups (16 rows) x 8 col-groups (16 cols); warp = 1 mblk x 2 nblk.
// smem: Wt[128][PITCH] tf32 (staged once/block) + ins[64][PITCH] tf32.
// ---------------------------------------------------------------------------
__global__ void __launch_bounds__(1024, 1)
gemm_mma_kernel(const float* __restrict__ Wl, const float* __restrict__ bl,
                const float* __restrict__ Wr, float* __restrict__ out, int N) {
    extern __shared__ float sm[];
    float* Wt  = sm;                   // [128][PITCH]
    float* ins = sm + 128 * PITCH;     // [64][PITCH]

    const int tid  = threadIdx.x;
    const int lane = tid & 31;
    const int wid  = tid >> 5;
    const int g    = lane >> 2;        // fragment row 0..7
    const int t    = lane & 3;         // fragment k sub 0..3
    const int wr   = wid >> 3;         // 0..3: rows wr*16
    const int wc   = wid & 7;          // 0..7: cols wc*16
    const int r0   = wr * 16;
    const int c0   = wc * 16;

    // Stage weights (tf32-rounded): Wt[n][k] = k<128 ? Wl[n][k] : Wr[n][k-128]
    for (int idx = tid; idx < 128 * 256; idx += 1024) {
        int n = idx >> 8;
        int k = idx & 255;
        float w = (k < 128) ? Wl[n * 128 + k] : Wr[n * 128 + (k - 128)];
        Wt[n * PITCH + k] = f2tf32f(w);
    }

    // Per-thread bias for epilogue: cols c0 + n*8 + 2t, +1
    float2 bias[2];
#pragma unroll
    for (int n = 0; n < 2; ++n) {
        int col = c0 + n * 8 + 2 * t;
        bias[n].x = __ldg(&bl[col]);
        bias[n].y = __ldg(&bl[col + 1]);
    }

    const float* Abase = ins + (r0 + g) * PITCH + t;
    const float* Bbase = Wt  + (c0 + g) * PITCH + t;

    const int ntiles = (N + 63) / 64;
    for (int tile = blockIdx.x; tile < ntiles; tile += gridDim.x) {
        __syncthreads();
        // Stage tile rows (tf32-rounded): ins[r][0:128]=mean_agg, [128:256]=h
        for (int i = tid; i < 64 * 64; i += 1024) {
            int r = i >> 6;
            int q = i & 63;
            int grow = tile * 64 + r;
            float4 v = make_float4(0.f, 0.f, 0.f, 0.f);
            if (grow < N) {
                v = (q < 32)
                  ? reinterpret_cast<const float4*>(g_agg)[(size_t)grow * 32 + q]
                  : reinterpret_cast<const float4*>(g_h)[(size_t)grow * 32 + (q - 32)];
            }
            float4 tv;
            tv.x = f2tf32f(v.x); tv.y = f2tf32f(v.y);
            tv.z = f2tf32f(v.z); tv.w = f2tf32f(v.w);
            *reinterpret_cast<float4*>(&ins[r * PITCH + q * 4]) = tv;
        }
        __syncthreads();

        float acc[2][4];
#pragma unroll
        for (int n = 0; n < 2; ++n)
#pragma unroll
            for (int i = 0; i < 4; ++i) acc[n][i] = 0.0f;

#pragma unroll 8
        for (int ks = 0; ks < 32; ++ks) {
            const float* ap = Abase + ks * 8;
            const float* bp = Bbase + ks * 8;

            uint32_t a[4];
            a[0] = __float_as_uint(ap[0]);
            a[1] = __float_as_uint(ap[8 * PITCH]);
            a[2] = __float_as_uint(ap[4]);
            a[3] = __float_as_uint(ap[8 * PITCH + 4]);

            uint32_t b[2][2];
#pragma unroll
            for (int n = 0; n < 2; ++n) {
                const float* p = bp + n * 8 * PITCH;
                b[n][0] = __float_as_uint(p[0]);
                b[n][1] = __float_as_uint(p[4]);
            }
#pragma unroll
            for (int n = 0; n < 2; ++n) {
                asm("mma.sync.aligned.m16n8k8.row.col.f32.tf32.tf32.f32 "
                    "{%0,%1,%2,%3}, {%4,%5,%6,%7}, {%8,%9}, {%0,%1,%2,%3};"
                    : "+f"(acc[n][0]), "+f"(acc[n][1]),
                      "+f"(acc[n][2]), "+f"(acc[n][3])
                    : "r"(a[0]), "r"(a[1]), "r"(a[2]), "r"(a[3]),
                      "r"(b[n][0]), "r"(b[n][1]));
            }
        }

        // Epilogue: rows {r0+g, r0+8+g}, cols c0+n*8+2t (+1)
        {
            int row0 = tile * 64 + r0 + g;
            int row1 = row0 + 8;
#pragma unroll
            for (int n = 0; n < 2; ++n) {
                int colh = (c0 + n * 8 + 2 * t) >> 1;
                if (row0 < N) {
                    float2 o0 = make_float2(acc[n][0] + bias[n].x,
                                            acc[n][1] + bias[n].y);
                    reinterpret_cast<float2*>(out)[(size_t)row0 * 64 + colh] = o0;
                }
                if (row1 < N) {
                    float2 o1 = make_float2(acc[n][2] + bias[n].x,
                                            acc[n][3] + bias[n].y);
                    reinterpret_cast<float2*>(out)[(size_t)row1 * 64 + colh] = o1;
                }
            }
        }
    }
}

// ---------------------------------------------------------------------------
extern "C" void kernel_launch(void* const* d_in, const int* in_sizes, int n_in,
                              void* d_out, int out_size) {
    const float* x     = (const float*)d_in[0];
    const int*   eidx  = (const int*)d_in[1];   // int32 (JAX x64 disabled)
    const float* mask  = (const float*)d_in[2];
    const float* gamma = (const float*)d_in[3];
    const float* beta  = (const float*)d_in[4];
    const float* Wl    = (const float*)d_in[5];
    const float* bl    = (const float*)d_in[6];
    const float* Wr    = (const float*)d_in[7];
    float*       out   = (float*)d_out;

    const int N = in_sizes[0] / D;
    const int E = in_sizes[1] / 2;

    ln_relu_drop_kernel<<<(N + 7) / 8, 256>>>(x, mask, gamma, beta, N);
    fill_kernel<<<(E + 255) / 256, 256>>>(eidx, E);
    aggregate_kernel<<<(N + 7) / 8, 256>>>(N);

    {
        int smem = (128 * PITCH + 64 * PITCH) * (int)sizeof(float);  // 199,680 B
        cudaFuncSetAttribute(gemm_mma_kernel, cudaFuncAttributeMaxDynamicSharedMemorySize, smem);
        int nsm = 148;
        cudaDeviceGetAttribute(&nsm, cudaDevAttrMultiProcessorCount, 0);
        gemm_mma_kernel<<<nsm, 1024, smem>>>(Wl, bl, Wr, out, N);
    }
}

// round 10
// speedup vs baseline: 2.2759x; 1.1534x over previous
#include <cuda_runtime.h>
#include <cstdint>

#define D 128
#define NMAX 100000
#define EMAX 600000
#define CAP 64
#define PITCH  260   // weights pitch: %32==4 -> conflict-free fragment rows
#define IPITCH 68    // ins chunk pitch: %32==4, 16B-aligned rows

// Scratch
__device__ __align__(16) float g_h[(size_t)NMAX * D];
__device__ __align__(16) float g_agg[(size_t)NMAX * D];   // mean_agg (tf32 vals)
__device__ int  g_cnt_i[NMAX];
__device__ int  g_bucket[(size_t)NMAX * CAP];
__device__ int2 g_ovf_edges[EMAX];
__device__ int  g_ovf_cnt;

__device__ __forceinline__ float f2tf32f(float f) {
    uint32_t t;
    asm("cvt.rna.tf32.f32 %0, %1;" : "=r"(t) : "f"(f));
    return __uint_as_float(t);
}
__device__ __forceinline__ uint32_t smem_u32(const void* p) {
    uint32_t a;
    asm("{ .reg .u64 t; cvta.to.shared.u64 t, %1; cvt.u32.u64 %0, t; }" : "=r"(a) : "l"(p));
    return a;
}
__device__ __forceinline__ void cp16(uint32_t dst, const void* src, bool pred) {
    int sz = pred ? 16 : 0;   // src-size 0 -> zero-fill
    asm volatile("cp.async.cg.shared.global [%0], [%1], 16, %2;"
                 :: "r"(dst), "l"(src), "r"(sz) : "memory");
}

// ---------------------------------------------------------------------------
// Kernel 1: LayerNorm -> ReLU -> dropout; h pre-rounded to tf32 (RNA).
// ---------------------------------------------------------------------------
__global__ void ln_relu_drop_kernel(const float* __restrict__ x,
                                    const float* __restrict__ mask,
                                    const float* __restrict__ gamma,
                                    const float* __restrict__ beta,
                                    int N) {
    int warp = threadIdx.x >> 5;
    int lane = threadIdx.x & 31;
    int row  = blockIdx.x * 8 + warp;
    if (blockIdx.x == 0 && threadIdx.x == 0) g_ovf_cnt = 0;
    if (row >= N) return;

    const float4 xv = reinterpret_cast<const float4*>(x)[row * 32 + lane];
    float s  = xv.x + xv.y + xv.z + xv.w;
    float ss = xv.x * xv.x + xv.y * xv.y + xv.z * xv.z + xv.w * xv.w;
#pragma unroll
    for (int o = 16; o > 0; o >>= 1) {
        s  += __shfl_xor_sync(0xFFFFFFFFu, s,  o);
        ss += __shfl_xor_sync(0xFFFFFFFFu, ss, o);
    }
    const float mu   = s * (1.0f / 128.0f);
    const float var  = ss * (1.0f / 128.0f) - mu * mu;
    const float rstd = rsqrtf(var + 1e-5f);

    const float4 g = reinterpret_cast<const float4*>(gamma)[lane];
    const float4 b = reinterpret_cast<const float4*>(beta)[lane];
    const float4 m = reinterpret_cast<const float4*>(mask)[row * 32 + lane];

    float4 hv;
    hv.x = f2tf32f(fmaxf((xv.x - mu) * rstd * g.x + b.x, 0.0f) * m.x);
    hv.y = f2tf32f(fmaxf((xv.y - mu) * rstd * g.y + b.y, 0.0f) * m.y);
    hv.z = f2tf32f(fmaxf((xv.z - mu) * rstd * g.z + b.z, 0.0f) * m.z);
    hv.w = f2tf32f(fmaxf((xv.w - mu) * rstd * g.w + b.w, 0.0f) * m.w);

    reinterpret_cast<float4*>(g_h)[row * 32 + lane] = hv;
    if (lane == 0) g_cnt_i[row] = 0;
}

// ---------------------------------------------------------------------------
// Kernel 2a: bucket fill (int atomics only).
// ---------------------------------------------------------------------------
__global__ void fill_kernel(const int* __restrict__ ei, int E) {
    int e = blockIdx.x * blockDim.x + threadIdx.x;
    if (e >= E) return;
    const int s = __ldg(&ei[e]);
    const int d = __ldg(&ei[E + e]);
    int pos = atomicAdd(&g_cnt_i[d], 1);
    if (pos < CAP) g_bucket[(size_t)d * CAP + pos] = s;
    else {
        int idx = atomicAdd(&g_ovf_cnt, 1);
        g_ovf_edges[idx] = make_int2(s, d);
    }
}

// ---------------------------------------------------------------------------
// Kernel 2b: gather-aggregate; writes mean pre-rounded to tf32.
// ---------------------------------------------------------------------------
__global__ void aggregate_kernel(int N) {
    int warp = threadIdx.x >> 5;
    int lane = threadIdx.x & 31;
    int d    = blockIdx.x * 8 + warp;
    if (d >= N) return;

    const int n  = g_cnt_i[d];
    const int nb = n < CAP ? n : CAP;
    const int* bk = &g_bucket[(size_t)d * CAP];

    float4 acc = make_float4(0.f, 0.f, 0.f, 0.f);
    int j = 0;
    for (; j + 2 <= nb; j += 2) {
        int s0 = __ldg(&bk[j]);
        int s1 = __ldg(&bk[j + 1]);
        float4 v0 = reinterpret_cast<const float4*>(g_h)[(size_t)s0 * 32 + lane];
        float4 v1 = reinterpret_cast<const float4*>(g_h)[(size_t)s1 * 32 + lane];
        acc.x += v0.x + v1.x; acc.y += v0.y + v1.y;
        acc.z += v0.z + v1.z; acc.w += v0.w + v1.w;
    }
    if (j < nb) {
        int s0 = __ldg(&bk[j]);
        float4 v0 = reinterpret_cast<const float4*>(g_h)[(size_t)s0 * 32 + lane];
        acc.x += v0.x; acc.y += v0.y; acc.z += v0.z; acc.w += v0.w;
    }
    const int novf = g_ovf_cnt;
    for (int t = 0; t < novf; ++t) {
        int2 p = g_ovf_edges[t];
        if (p.y == d) {
            float4 v = reinterpret_cast<const float4*>(g_h)[(size_t)p.x * 32 + lane];
            acc.x += v.x; acc.y += v.y; acc.z += v.z; acc.w += v.w;
        }
    }
    const float inv = 1.0f / fmaxf((float)n, 1.0f);
    float4 o;
    o.x = f2tf32f(acc.x * inv);
    o.y = f2tf32f(acc.y * inv);
    o.z = f2tf32f(acc.z * inv);
    o.w = f2tf32f(acc.w * inv);
    reinterpret_cast<float4*>(g_agg)[(size_t)d * 32 + lane] = o;
}

// ---------------------------------------------------------------------------
// Kernel 3: tf32 mma.sync GEMM, cp.async double-buffered K chunks.
//   out = [mean_agg | h] (Nx256) @ Wcat^T + b_l
// Block tile M=128, N=128; K in 4 chunks of 64. 1024 threads = 32 warps:
//   4 row-groups (32r = 2 mblk) x 8 col-groups (16c = 2 nblk); warp 2m x 2n.
// smem: Wt[128][PITCH] (once/block) + 2 x ins[128][IPITCH] chunk buffers.
// ---------------------------------------------------------------------------
__global__ void __launch_bounds__(1024, 1)
gemm_mma_kernel(const float* __restrict__ Wl, const float* __restrict__ bl,
                const float* __restrict__ Wr, float* __restrict__ out, int N) {
    extern __shared__ float sm[];
    float* Wt   = sm;                          // [128][PITCH]
    float* bufs = sm + 128 * PITCH;            // 2 x [128][IPITCH]
    const uint32_t bufs_u32 = smem_u32(bufs);

    const int tid  = threadIdx.x;
    const int lane = tid & 31;
    const int wid  = tid >> 5;
    const int g    = lane >> 2;
    const int t    = lane & 3;
    const int mg   = wid >> 3;        // 0..3: rows mg*32
    const int ng   = wid & 7;         // 0..7: cols ng*16
    const int r0   = mg * 32;
    const int c0   = ng * 16;

    // Stage weights (tf32-rounded): Wt[n][k]
    for (int idx = tid; idx < 128 * 256; idx += 1024) {
        int n = idx >> 8;
        int k = idx & 255;
        float w = (k < 128) ? Wl[n * 128 + k] : Wr[n * 128 + (k - 128)];
        Wt[n * PITCH + k] = f2tf32f(w);
    }

    float2 bias[2];
#pragma unroll
    for (int n = 0; n < 2; ++n) {
        int col = c0 + n * 8 + 2 * t;
        bias[n].x = __ldg(&bl[col]);
        bias[n].y = __ldg(&bl[col + 1]);
    }

    const int sr  = tid >> 4;          // staging row 0..63 (u adds +64)
    const int sfo = tid & 15;          // staging float4 col 0..15
    const int ntiles = (N + 127) / 128;

    for (int tile = blockIdx.x; tile < ntiles; tile += gridDim.x) {
        const int rowbase = tile * 128;

        // prefetch chunk 0 (cols 0..63 of [mean_agg|h] = g_agg cols 0..63)
#pragma unroll
        for (int u = 0; u < 2; ++u) {
            int r = sr + u * 64;
            int grow = rowbase + r;
            const float* src = g_agg + (size_t)grow * 128 + sfo * 4;
            uint32_t dst = bufs_u32 + (uint32_t)(r * IPITCH + sfo * 4) * 4u;
            cp16(dst, src, grow < N);
        }
        asm volatile("cp.async.commit_group;" ::: "memory");

        float acc[2][2][4];
#pragma unroll
        for (int m = 0; m < 2; ++m)
#pragma unroll
            for (int n = 0; n < 2; ++n)
#pragma unroll
                for (int i = 0; i < 4; ++i) acc[m][n][i] = 0.0f;

#pragma unroll
        for (int c = 0; c < 4; ++c) {
            if (c < 3) {
                const int cc = c + 1;
#pragma unroll
                for (int u = 0; u < 2; ++u) {
                    int r = sr + u * 64;
                    int grow = rowbase + r;
                    int colb = cc * 64 + sfo * 4;   // 64..255
                    const float* src = (colb < 128)
                        ? g_agg + (size_t)grow * 128 + colb
                        : g_h   + (size_t)grow * 128 + (colb - 128);
                    uint32_t dst = bufs_u32
                        + (uint32_t)(((cc & 1) * 128 + r) * IPITCH + sfo * 4) * 4u;
                    cp16(dst, src, grow < N);
                }
                asm volatile("cp.async.commit_group;" ::: "memory");
                asm volatile("cp.async.wait_group 1;" ::: "memory");
            } else {
                asm volatile("cp.async.wait_group 0;" ::: "memory");
            }
            __syncthreads();

            const float* Abase = bufs + (c & 1) * 128 * IPITCH + (r0 + g) * IPITCH + t;
            const float* Bbase = Wt + (c0 + g) * PITCH + c * 64 + t;

#pragma unroll
            for (int ks = 0; ks < 8; ++ks) {
                const float* ap = Abase + ks * 8;
                const float* bp = Bbase + ks * 8;

                uint32_t a[2][4];
#pragma unroll
                for (int m = 0; m < 2; ++m) {
                    const float* p = ap + m * 16 * IPITCH;
                    a[m][0] = __float_as_uint(p[0]);
                    a[m][1] = __float_as_uint(p[8 * IPITCH]);
                    a[m][2] = __float_as_uint(p[4]);
                    a[m][3] = __float_as_uint(p[8 * IPITCH + 4]);
                }
                uint32_t b[2][2];
#pragma unroll
                for (int n = 0; n < 2; ++n) {
                    const float* p = bp + n * 8 * PITCH;
                    b[n][0] = __float_as_uint(p[0]);
                    b[n][1] = __float_as_uint(p[4]);
                }
#pragma unroll
                for (int m = 0; m < 2; ++m)
#pragma unroll
                    for (int n = 0; n < 2; ++n) {
                        asm("mma.sync.aligned.m16n8k8.row.col.f32.tf32.tf32.f32 "
                            "{%0,%1,%2,%3}, {%4,%5,%6,%7}, {%8,%9}, {%0,%1,%2,%3};"
                            : "+f"(acc[m][n][0]), "+f"(acc[m][n][1]),
                              "+f"(acc[m][n][2]), "+f"(acc[m][n][3])
                            : "r"(a[m][0]), "r"(a[m][1]), "r"(a[m][2]), "r"(a[m][3]),
                              "r"(b[n][0]), "r"(b[n][1]));
                    }
            }
            __syncthreads();
        }

        // Epilogue: rows {r0 + m*16 + g, +8}, cols c0 + n*8 + 2t (+1)
#pragma unroll
        for (int m = 0; m < 2; ++m) {
            int row0 = rowbase + r0 + m * 16 + g;
            int row1 = row0 + 8;
#pragma unroll
            for (int n = 0; n < 2; ++n) {
                int colh = (c0 + n * 8 + 2 * t) >> 1;
                if (row0 < N) {
                    float2 o0 = make_float2(acc[m][n][0] + bias[n].x,
                                            acc[m][n][1] + bias[n].y);
                    reinterpret_cast<float2*>(out)[(size_t)row0 * 64 + colh] = o0;
                }
                if (row1 < N) {
                    float2 o1 = make_float2(acc[m][n][2] + bias[n].x,
                                            acc[m][n][3] + bias[n].y);
                    reinterpret_cast<float2*>(out)[(size_t)row1 * 64 + colh] = o1;
                }
            }
        }
    }
}

// ---------------------------------------------------------------------------
extern "C" void kernel_launch(void* const* d_in, const int* in_sizes, int n_in,
                              void* d_out, int out_size) {
    const float* x     = (const float*)d_in[0];
    const int*   eidx  = (const int*)d_in[1];   // int32 (JAX x64 disabled)
    const float* mask  = (const float*)d_in[2];
    const float* gamma = (const float*)d_in[3];
    const float* beta  = (const float*)d_in[4];
    const float* Wl    = (const float*)d_in[5];
    const float* bl    = (const float*)d_in[6];
    const float* Wr    = (const float*)d_in[7];
    float*       out   = (float*)d_out;

    const int N = in_sizes[0] / D;
    const int E = in_sizes[1] / 2;

    ln_relu_drop_kernel<<<(N + 7) / 8, 256>>>(x, mask, gamma, beta, N);
    fill_kernel<<<(E + 255) / 256, 256>>>(eidx, E);
    aggregate_kernel<<<(N + 7) / 8, 256>>>(N);

    {
        int smem = (128 * PITCH + 2 * 128 * IPITCH) * (int)sizeof(float);  // 202,752 B
        cudaFuncSetAttribute(gemm_mma_kernel, cudaFuncAttributeMaxDynamicSharedMemorySize, smem);
        int nsm = 148;
        cudaDeviceGetAttribute(&nsm, cudaDevAttrMultiProcessorCount, 0);
        gemm_mma_kernel<<<nsm, 1024, smem>>>(Wl, bl, Wr, out, N);
    }
}